// round 16
// baseline (speedup 1.0000x reference)
#include <cuda_runtime.h>
#include <cuda_bf16.h>
#include <stdint.h>
#include <math.h>

#define D 256
#define MAXN 16384
#define MAXK 8192

// ---------------- scratch (module globals; no runtime allocation) ----------------
__device__ float          g_C[MAXK];          // per-code sum c^2 (exact sequential)
__device__ float          g_rowss[MAXN];      // per-row sum d^2
__device__ double         g_part[64];         // loss partials
__device__ __nv_bfloat16  g_zb[MAXN * D];     // bf16 copy of z
__device__ __nv_bfloat16  g_cbb[MAXK * D];    // bf16 copy of codebook

// ================= tiny PTX helpers (all sm_80-legal) =================
__device__ __forceinline__ void cpa16(uint32_t dst, const void* src) {
    asm volatile("cp.async.cg.shared.global [%0], [%1], 16;" :: "r"(dst), "l"(src) : "memory");
}
#define CP_COMMIT() asm volatile("cp.async.commit_group;" ::: "memory")
#define CP_WAIT(n)  asm volatile("cp.async.wait_group %0;" :: "n"(n) : "memory")

__device__ __forceinline__ uint32_t smem_u32(const void* p) {
    uint32_t a;
    asm("{ .reg .u64 t; cvta.to.shared.u64 t, %1; cvt.u32.u64 %0, t; }" : "=r"(a) : "l"(p));
    return a;
}
__device__ __forceinline__ void ldsm_x4(uint32_t r[4], uint32_t addr) {
    asm volatile("ldmatrix.sync.aligned.m8n8.x4.shared.b16 {%0,%1,%2,%3}, [%4];"
        : "=r"(r[0]), "=r"(r[1]), "=r"(r[2]), "=r"(r[3]) : "r"(addr));
}
// D += A(16x16 bf16, row-major) * B(16x8 col-major)
__device__ __forceinline__ void mma_bf16(float c[4], const uint32_t a[4], uint32_t b0, uint32_t b1) {
    asm volatile(
        "mma.sync.aligned.m16n8k16.row.col.f32.bf16.bf16.f32 "
        "{%0,%1,%2,%3}, {%4,%5,%6,%7}, {%8,%9}, {%0,%1,%2,%3};"
        : "+f"(c[0]), "+f"(c[1]), "+f"(c[2]), "+f"(c[3])
        : "r"(a[0]), "r"(a[1]), "r"(a[2]), "r"(a[3]), "r"(b0), "r"(b1));
}

// ===== fused prep: flat bf16 conversion (blocks 0..NCVT) + codebook sumsq =====
__global__ void k_prep(const float* __restrict__ z, const float* __restrict__ cb,
                       int nz4, int nc4, int ncvt_blocks, int K) {
    if (blockIdx.x < (unsigned)ncvt_blocks) {
        int i = blockIdx.x * blockDim.x + threadIdx.x;
        const float4* src;
        __nv_bfloat162* dst;
        int j;
        if (i < nz4) {
            src = reinterpret_cast<const float4*>(z);
            dst = reinterpret_cast<__nv_bfloat162*>(g_zb);
            j = i;
        } else if (i < nz4 + nc4) {
            src = reinterpret_cast<const float4*>(cb);
            dst = reinterpret_cast<__nv_bfloat162*>(g_cbb);
            j = i - nz4;
        } else return;
        float4 v = src[j];
        dst[j * 2]     = __floats2bfloat162_rn(v.x, v.y);
        dst[j * 2 + 1] = __floats2bfloat162_rn(v.z, v.w);
    } else {
        int r = (blockIdx.x - ncvt_blocks) * blockDim.x + threadIdx.x;
        if (r >= K) return;
        const float4* p = reinterpret_cast<const float4*>(cb + (size_t)r * D);
        float a = 0.f;
#pragma unroll 8
        for (int i = 0; i < D / 4; ++i) {
            float4 v = p[i];
            a = __fadd_rn(a, __fmul_rn(v.x, v.x));
            a = __fadd_rn(a, __fmul_rn(v.y, v.y));
            a = __fadd_rn(a, __fmul_rn(v.z, v.z));
            a = __fadd_rn(a, __fmul_rn(v.w, v.w));
        }
        g_C[r] = a;
    }
}

// === stage 1: HMMA bf16 GEMM + top-4 + in-kernel exact rescore + FINISH ===
#define PADB 528
#define CHUNK 64
#define B_BYTES (CHUNK * PADB)            // 33792
#define SM_B(j) ((j) * B_BYTES)
#define SM_TOT  (2 * B_BYTES)             // 67584

__global__ __launch_bounds__(256, 1)
void k_gemm_topk(const float* __restrict__ z, const float* __restrict__ cb,
                 float* __restrict__ zq, float* __restrict__ idxout, int K) {
    extern __shared__ char sm[];
    const uint32_t sb = smem_u32(sm);
    const int tid = threadIdx.x;
    const int lid = tid & 31, wid = tid >> 5;
    const int warpM = wid >> 1, warpN = wid & 1;  // 4M x 2N
    const int g = lid >> 2, tg = lid & 3;
    const int row0 = blockIdx.x * 128;
    const int nchunks = K / CHUNK;                // 128

    // ---- prefetch B chunk 0 ----
    {
#pragma unroll
        for (int t = 0; t < 8; ++t) {
            int e = t * 256 + tid;               // 0..2047
            int r = e >> 5, j = e & 31;
            cpa16(sb + SM_B(0) + r * PADB + j * 16, g_cbb + (size_t)r * D + j * 8);
        }
        CP_COMMIT();
    }

    // ---- load A fragments straight from global into registers (one-time) ----
    uint32_t aR[2][16][4];
    {
        const uint32_t* w = reinterpret_cast<const uint32_t*>(g_zb);
#pragma unroll
        for (int mt = 0; mt < 2; ++mt) {
            const uint32_t rA = (uint32_t)(row0 + warpM * 32 + mt * 16 + g) * 128u;
            const uint32_t rB = rA + 8u * 128u;
#pragma unroll
            for (int ks = 0; ks < 16; ++ks) {
                aR[mt][ks][0] = __ldg(w + rA + ks * 8 + tg);
                aR[mt][ks][1] = __ldg(w + rB + ks * 8 + tg);
                aR[mt][ks][2] = __ldg(w + rA + ks * 8 + 4 + tg);
                aR[mt][ks][3] = __ldg(w + rB + ks * 8 + 4 + tg);
            }
        }
    }

    const int bCode = (lid & 7) + ((lid >> 4) << 3);
    const int bKoff = ((lid >> 3) & 1) * 16;
    const uint32_t bLaneOff = (uint32_t)(warpN * 32 + bCode) * PADB + bKoff;

    // per-thread top-2 for each of its 4 tracked rows
    float bv[4][2];
    int   bi[4][2];
#pragma unroll
    for (int i = 0; i < 4; ++i) { bv[i][0] = bv[i][1] = -3.4e38f; bi[i][0] = bi[i][1] = 0; }

    for (int i = 0; i < nchunks; ++i) {
        const int s = i & 1;
        if (i + 1 < nchunks) {
            const __nv_bfloat16* csrc = g_cbb + (size_t)(i + 1) * CHUNK * D;
            const uint32_t dstb = sb + SM_B(1 - s);
#pragma unroll
            for (int t = 0; t < 8; ++t) {
                int e = t * 256 + tid;
                int r = e >> 5, j = e & 31;
                cpa16(dstb + r * PADB + j * 16, csrc + (size_t)r * D + j * 8);
            }
            CP_COMMIT();
            CP_WAIT(1);
        } else {
            CP_WAIT(0);
        }
        __syncthreads();

        const uint32_t bufb = sb + SM_B(s) + bLaneOff;

        float acc[2][4][4];
#pragma unroll
        for (int mt = 0; mt < 2; ++mt)
#pragma unroll
            for (int nt = 0; nt < 4; ++nt)
#pragma unroll
                for (int q = 0; q < 4; ++q) acc[mt][nt][q] = 0.f;

#pragma unroll
        for (int ks = 0; ks < 16; ++ks) {
            uint32_t b0[4], b1[4];
            ldsm_x4(b0, bufb + ks * 32);                 // codes +0..15
            ldsm_x4(b1, bufb + 16 * PADB + ks * 32);     // codes +16..31
#pragma unroll
            for (int mt = 0; mt < 2; ++mt) {
                mma_bf16(acc[mt][0], aR[mt][ks], b0[0], b0[1]);
                mma_bf16(acc[mt][1], aR[mt][ks], b0[2], b0[3]);
                mma_bf16(acc[mt][2], aR[mt][ks], b1[0], b1[1]);
                mma_bf16(acc[mt][3], aR[mt][ks], b1[2], b1[3]);
            }
        }

        // ---- top-2 update (lazy index) ----
        const int cbase0 = i * CHUNK + warpN * 32 + tg * 2;
#pragma unroll
        for (int mt = 0; mt < 2; ++mt) {
#pragma unroll
            for (int nt = 0; nt < 4; ++nt) {
#pragma unroll
                for (int q = 0; q < 4; ++q) {
                    const int sl = mt * 2 + (q >> 1);
                    const float v = acc[mt][nt][q];
                    if (v > bv[sl][1]) {
                        const int ci = cbase0 + nt * 8 + (q & 1);
                        if (v > bv[sl][0]) {
                            bv[sl][1] = bv[sl][0]; bi[sl][1] = bi[sl][0];
                            bv[sl][0] = v;         bi[sl][0] = ci;
                        } else {
                            bv[sl][1] = v;         bi[sl][1] = ci;
                        }
                    }
                }
            }
        }
        __syncthreads();
    }

    // ---- merge: 8 owners x top2 per row -> top4 per row, kept in smem ----
    float* mv = reinterpret_cast<float*>(sm);            // 16*128 floats = 8KB
    int*   mi = reinterpret_cast<int*>(sm + 8192);       // 8KB
    int*   candS = reinterpret_cast<int*>(sm + 16384);   // 512 ints = 2KB
    int*   winS  = reinterpret_cast<int*>(sm + 16384 + 2048); // 128 ints
    const int owner = warpN * 4 + tg;                    // 0..7
#pragma unroll
    for (int sl = 0; sl < 4; ++sl) {
        const int srow = warpM * 32 + (sl >> 1) * 16 + (sl & 1) * 8 + g;
#pragma unroll
        for (int j = 0; j < 2; ++j) {
            mv[(owner * 2 + j) * 128 + srow] = bv[sl][j];
            mi[(owner * 2 + j) * 128 + srow] = bi[sl][j];
        }
    }
    __syncthreads();
    if (tid < 128) {
        float fv0=-3.4e38f, fv1=-3.4e38f, fv2=-3.4e38f, fv3=-3.4e38f;
        int   fi0=0, fi1=0, fi2=0, fi3=0;
#pragma unroll
        for (int e = 0; e < 16; ++e) {
            float v = mv[e * 128 + tid];
            if (v > fv3) {
                int ci = mi[e * 128 + tid];
                if (v > fv0)      { fv3=fv2;fi3=fi2; fv2=fv1;fi2=fi1; fv1=fv0;fi1=fi0; fv0=v;fi0=ci; }
                else if (v > fv1) { fv3=fv2;fi3=fi2; fv2=fv1;fi2=fi1; fv1=v;fi1=ci; }
                else if (v > fv2) { fv3=fv2;fi3=fi2; fv2=v;fi2=ci; }
                else              { fv3=v;fi3=ci; }
            }
        }
        candS[tid * 4 + 0] = fi0;
        candS[tid * 4 + 1] = fi1;
        candS[tid * 4 + 2] = fi2;
        candS[tid * 4 + 3] = fi3;
    }
    __syncthreads();

    // ---- in-kernel exact rescore: 512 jobs over 256 threads (2 each) ----
    // Bit-identical to the R1 full scan: A = sequential sum(z^2), dot =
    // sequential fmaf, score = fl(fl(A-2B)+C); min-by-(value,index).
#pragma unroll
    for (int half = 0; half < 2; ++half) {
        const int j = tid + half * 256;       // job id 0..511
        const int row = j >> 2, m = j & 3;    // local row, candidate slot
        int c = candS[j];
        const float4* zr = reinterpret_cast<const float4*>(z + (size_t)(row0 + row) * D);
        const float4* cr = reinterpret_cast<const float4*>(cb + (size_t)c * D);
        float A = 0.f, acc2 = 0.f;
#pragma unroll 8
        for (int i = 0; i < D / 4; ++i) {
            float4 a = __ldg(zr + i);
            float4 b = __ldg(cr + i);
            A = __fadd_rn(A, __fmul_rn(a.x, a.x));
            A = __fadd_rn(A, __fmul_rn(a.y, a.y));
            A = __fadd_rn(A, __fmul_rn(a.z, a.z));
            A = __fadd_rn(A, __fmul_rn(a.w, a.w));
            acc2 = __fmaf_rn(a.x, b.x, acc2);
            acc2 = __fmaf_rn(a.y, b.y, acc2);
            acc2 = __fmaf_rn(a.z, b.z, acc2);
            acc2 = __fmaf_rn(a.w, b.w, acc2);
        }
        float s = __fadd_rn(__fmaf_rn(-2.f, acc2, A), g_C[c]);
#pragma unroll
        for (int o = 1; o < 4; o <<= 1) {
            float sv = __shfl_xor_sync(0xffffffffu, s, o);
            int   ci = __shfl_xor_sync(0xffffffffu, c, o);
            if (sv < s || (sv == s && ci < c)) { s = sv; c = ci; }
        }
        if (m == 0) winS[row] = c;
    }
    __syncthreads();

    // ---- fused finish: 2 threads per row, 128 elems each (rows L1/L2-warm) ----
    {
        const int frow = tid >> 1;            // 0..127
        const int fhalf = tid & 1;            // elem range [fhalf*128, +128)
        const int code = winS[frow];
        const int grow = row0 + frow;
        const float2* zp2 = reinterpret_cast<const float2*>(z + (size_t)grow * D) + fhalf * 64;
        const float2* cp2 = reinterpret_cast<const float2*>(cb + (size_t)code * D) + fhalf * 64;

        // pass 1: partial sum of d^2 over this half
        float ss = 0.f;
#pragma unroll 8
        for (int i = 0; i < 64; ++i) {
            float2 a = __ldg(zp2 + i);
            float2 b = __ldg(cp2 + i);
            float d0 = __fsub_rn(b.x, a.x);
            float d1 = __fsub_rn(b.y, a.y);
            ss = __fadd_rn(ss, __fadd_rn(__fmul_rn(d0, d0), __fmul_rn(d1, d1)));
        }
        // deterministic 2-lane combine: ssum = half0 + half1
        float other = __shfl_xor_sync(0xffffffffu, ss, 1);
        float s0 = fhalf ? other : ss;
        float s1 = fhalf ? ss : other;
        float ssum = __fadd_rn(s0, s1);

        float mag = __fsqrt_rn(ssum);
        float den = __fadd_rn(mag, 1e-8f);

        // pass 2: recompute d and write z_q for this half
        float2* zqo = reinterpret_cast<float2*>(zq + (size_t)grow * D) + fhalf * 64;
#pragma unroll 8
        for (int i = 0; i < 64; ++i) {
            float2 a = __ldg(zp2 + i);
            float2 b = __ldg(cp2 + i);
            float d0 = __fsub_rn(b.x, a.x);
            float d1 = __fsub_rn(b.y, a.y);
            float2 o;
            o.x = __fadd_rn(a.x, __fmul_rn(mag, __fdiv_rn(d0, den)));
            o.y = __fadd_rn(a.y, __fmul_rn(mag, __fdiv_rn(d1, den)));
            zqo[i] = o;
        }
        if (fhalf == 0) {
            g_rowss[grow] = ssum;
            idxout[grow] = (float)code;
        }
    }
}

// ============ loss stage 1: 64 blocks, fixed-order partial sums ============
__global__ void k_loss_part(int n) {
    const int b = blockIdx.x;              // 0..63
    const int per = n / 64;                // 256 rows per block
    __shared__ double sred[256];
    double s = 0.0;
    for (int i = threadIdx.x; i < per; i += 256) s += (double)g_rowss[b * per + i];
    sred[threadIdx.x] = s;
    __syncthreads();
    for (int o = 128; o > 0; o >>= 1) {
        if (threadIdx.x < o) sred[threadIdx.x] += sred[threadIdx.x + o];
        __syncthreads();
    }
    if (threadIdx.x == 0) g_part[b] = sred[0];
}

// ============ loss stage 2: deterministic final sum ============
__global__ void k_loss_final(float* __restrict__ out_loss, int n) {
    if (threadIdx.x == 0) {
        double s = 0.0;
        for (int i = 0; i < 64; ++i) s += g_part[i];
        double mean = s / ((double)n * (double)D);
        out_loss[0] = (float)(1.25 * mean);
    }
}

extern "C" void kernel_launch(void* const* d_in, const int* in_sizes, int n_in,
                              void* d_out, int out_size) {
    const float* z  = (const float*)d_in[0];
    const float* cb = (const float*)d_in[1];
    const int n = in_sizes[0] / D;   // 16384
    const int K = in_sizes[1] / D;   // 8192

    float* out    = (float*)d_out;
    float* zq     = out;
    float* loss   = out + (size_t)n * D;
    float* idxout = loss + 1;

    cudaFuncSetAttribute(k_gemm_topk, cudaFuncAttributeMaxDynamicSharedMemorySize, SM_TOT);

    const int nz4 = n * D / 4, nc4 = K * D / 4;
    const int ncvt = (nz4 + nc4 + 255) / 256;
    const int nsq  = (K + 255) / 256;
    k_prep<<<ncvt + nsq, 256>>>(z, cb, nz4, nc4, ncvt, K);
    k_gemm_topk<<<n / 128, 256, SM_TOT>>>(z, cb, zq, idxout, K);
    k_loss_part<<<64, 256>>>(n);
    k_loss_final<<<1, 32>>>(loss, n);
}

// round 17
// speedup vs baseline: 1.1769x; 1.1769x over previous
#include <cuda_runtime.h>
#include <cuda_bf16.h>
#include <stdint.h>
#include <math.h>

#define D 256
#define MAXN 16384
#define MAXK 8192

// ---------------- scratch (module globals; no runtime allocation) ----------------
__device__ float          g_C[MAXK];          // per-code sum c^2 (exact sequential)
__device__ int            g_idx[MAXN];        // final argmin per row
__device__ float          g_rowss[MAXN];      // per-row sum d^2
__device__ double         g_part[64];         // loss partials
__device__ unsigned int   g_done;             // last-block-done counter
__device__ __nv_bfloat16  g_zb[MAXN * D];     // bf16 copy of z
__device__ __nv_bfloat16  g_cbb[MAXK * D];    // bf16 copy of codebook

// ================= tiny PTX helpers (all sm_80-legal) =================
__device__ __forceinline__ void cpa16(uint32_t dst, const void* src) {
    asm volatile("cp.async.cg.shared.global [%0], [%1], 16;" :: "r"(dst), "l"(src) : "memory");
}
#define CP_COMMIT() asm volatile("cp.async.commit_group;" ::: "memory")
#define CP_WAIT(n)  asm volatile("cp.async.wait_group %0;" :: "n"(n) : "memory")

__device__ __forceinline__ uint32_t smem_u32(const void* p) {
    uint32_t a;
    asm("{ .reg .u64 t; cvta.to.shared.u64 t, %1; cvt.u32.u64 %0, t; }" : "=r"(a) : "l"(p));
    return a;
}
__device__ __forceinline__ void ldsm_x4(uint32_t r[4], uint32_t addr) {
    asm volatile("ldmatrix.sync.aligned.m8n8.x4.shared.b16 {%0,%1,%2,%3}, [%4];"
        : "=r"(r[0]), "=r"(r[1]), "=r"(r[2]), "=r"(r[3]) : "r"(addr));
}
// D += A(16x16 bf16, row-major) * B(16x8 col-major)
__device__ __forceinline__ void mma_bf16(float c[4], const uint32_t a[4], uint32_t b0, uint32_t b1) {
    asm volatile(
        "mma.sync.aligned.m16n8k16.row.col.f32.bf16.bf16.f32 "
        "{%0,%1,%2,%3}, {%4,%5,%6,%7}, {%8,%9}, {%0,%1,%2,%3};"
        : "+f"(c[0]), "+f"(c[1]), "+f"(c[2]), "+f"(c[3])
        : "r"(a[0]), "r"(a[1]), "r"(a[2]), "r"(a[3]), "r"(b0), "r"(b1));
}

// ===== fused prep: flat bf16 conversion (blocks 0..NCVT) + codebook sumsq =====
__global__ void k_prep(const float* __restrict__ z, const float* __restrict__ cb,
                       int nz4, int nc4, int ncvt_blocks, int K) {
    if (blockIdx.x == 0 && threadIdx.x == 0) g_done = 0;   // reset loss counter
    if (blockIdx.x < (unsigned)ncvt_blocks) {
        int i = blockIdx.x * blockDim.x + threadIdx.x;
        const float4* src;
        __nv_bfloat162* dst;
        int j;
        if (i < nz4) {
            src = reinterpret_cast<const float4*>(z);
            dst = reinterpret_cast<__nv_bfloat162*>(g_zb);
            j = i;
        } else if (i < nz4 + nc4) {
            src = reinterpret_cast<const float4*>(cb);
            dst = reinterpret_cast<__nv_bfloat162*>(g_cbb);
            j = i - nz4;
        } else return;
        float4 v = src[j];
        dst[j * 2]     = __floats2bfloat162_rn(v.x, v.y);
        dst[j * 2 + 1] = __floats2bfloat162_rn(v.z, v.w);
    } else {
        int r = (blockIdx.x - ncvt_blocks) * blockDim.x + threadIdx.x;
        if (r >= K) return;
        const float4* p = reinterpret_cast<const float4*>(cb + (size_t)r * D);
        float a = 0.f;
#pragma unroll 8
        for (int i = 0; i < D / 4; ++i) {
            float4 v = p[i];
            a = __fadd_rn(a, __fmul_rn(v.x, v.x));
            a = __fadd_rn(a, __fmul_rn(v.y, v.y));
            a = __fadd_rn(a, __fmul_rn(v.z, v.z));
            a = __fadd_rn(a, __fmul_rn(v.w, v.w));
        }
        g_C[r] = a;
    }
}

// ========== stage 1: HMMA bf16 GEMM + top-4 + IN-KERNEL exact rescore ==========
// (R15 version, verbatim — best measured.)
#define PADB 528
#define CHUNK 64
#define B_BYTES (CHUNK * PADB)            // 33792
#define SM_B(j) ((j) * B_BYTES)
#define SM_TOT  (2 * B_BYTES)             // 67584

__global__ __launch_bounds__(256, 1)
void k_gemm_topk(const float* __restrict__ z, const float* __restrict__ cb, int K) {
    extern __shared__ char sm[];
    const uint32_t sb = smem_u32(sm);
    const int tid = threadIdx.x;
    const int lid = tid & 31, wid = tid >> 5;
    const int warpM = wid >> 1, warpN = wid & 1;  // 4M x 2N
    const int g = lid >> 2, tg = lid & 3;
    const int row0 = blockIdx.x * 128;
    const int nchunks = K / CHUNK;                // 128

    // ---- prefetch B chunk 0 ----
    {
#pragma unroll
        for (int t = 0; t < 8; ++t) {
            int e = t * 256 + tid;               // 0..2047
            int r = e >> 5, j = e & 31;
            cpa16(sb + SM_B(0) + r * PADB + j * 16, g_cbb + (size_t)r * D + j * 8);
        }
        CP_COMMIT();
    }

    // ---- load A fragments straight from global into registers (one-time) ----
    uint32_t aR[2][16][4];
    {
        const uint32_t* w = reinterpret_cast<const uint32_t*>(g_zb);
#pragma unroll
        for (int mt = 0; mt < 2; ++mt) {
            const uint32_t rA = (uint32_t)(row0 + warpM * 32 + mt * 16 + g) * 128u;
            const uint32_t rB = rA + 8u * 128u;
#pragma unroll
            for (int ks = 0; ks < 16; ++ks) {
                aR[mt][ks][0] = __ldg(w + rA + ks * 8 + tg);
                aR[mt][ks][1] = __ldg(w + rB + ks * 8 + tg);
                aR[mt][ks][2] = __ldg(w + rA + ks * 8 + 4 + tg);
                aR[mt][ks][3] = __ldg(w + rB + ks * 8 + 4 + tg);
            }
        }
    }

    const int bCode = (lid & 7) + ((lid >> 4) << 3);
    const int bKoff = ((lid >> 3) & 1) * 16;
    const uint32_t bLaneOff = (uint32_t)(warpN * 32 + bCode) * PADB + bKoff;

    // per-thread top-2 for each of its 4 tracked rows
    float bv[4][2];
    int   bi[4][2];
#pragma unroll
    for (int i = 0; i < 4; ++i) { bv[i][0] = bv[i][1] = -3.4e38f; bi[i][0] = bi[i][1] = 0; }

    for (int i = 0; i < nchunks; ++i) {
        const int s = i & 1;
        if (i + 1 < nchunks) {
            const __nv_bfloat16* csrc = g_cbb + (size_t)(i + 1) * CHUNK * D;
            const uint32_t dstb = sb + SM_B(1 - s);
#pragma unroll
            for (int t = 0; t < 8; ++t) {
                int e = t * 256 + tid;
                int r = e >> 5, j = e & 31;
                cpa16(dstb + r * PADB + j * 16, csrc + (size_t)r * D + j * 8);
            }
            CP_COMMIT();
            CP_WAIT(1);
        } else {
            CP_WAIT(0);
        }
        __syncthreads();

        const uint32_t bufb = sb + SM_B(s) + bLaneOff;

        float acc[2][4][4];
#pragma unroll
        for (int mt = 0; mt < 2; ++mt)
#pragma unroll
            for (int nt = 0; nt < 4; ++nt)
#pragma unroll
                for (int q = 0; q < 4; ++q) acc[mt][nt][q] = 0.f;

#pragma unroll
        for (int ks = 0; ks < 16; ++ks) {
            uint32_t b0[4], b1[4];
            ldsm_x4(b0, bufb + ks * 32);                 // codes +0..15
            ldsm_x4(b1, bufb + 16 * PADB + ks * 32);     // codes +16..31
#pragma unroll
            for (int mt = 0; mt < 2; ++mt) {
                mma_bf16(acc[mt][0], aR[mt][ks], b0[0], b0[1]);
                mma_bf16(acc[mt][1], aR[mt][ks], b0[2], b0[3]);
                mma_bf16(acc[mt][2], aR[mt][ks], b1[0], b1[1]);
                mma_bf16(acc[mt][3], aR[mt][ks], b1[2], b1[3]);
            }
        }

        // ---- top-2 update (lazy index) ----
        const int cbase0 = i * CHUNK + warpN * 32 + tg * 2;
#pragma unroll
        for (int mt = 0; mt < 2; ++mt) {
#pragma unroll
            for (int nt = 0; nt < 4; ++nt) {
#pragma unroll
                for (int q = 0; q < 4; ++q) {
                    const int sl = mt * 2 + (q >> 1);
                    const float v = acc[mt][nt][q];
                    if (v > bv[sl][1]) {
                        const int ci = cbase0 + nt * 8 + (q & 1);
                        if (v > bv[sl][0]) {
                            bv[sl][1] = bv[sl][0]; bi[sl][1] = bi[sl][0];
                            bv[sl][0] = v;         bi[sl][0] = ci;
                        } else {
                            bv[sl][1] = v;         bi[sl][1] = ci;
                        }
                    }
                }
            }
        }
        __syncthreads();
    }

    // ---- merge: 8 owners x top2 per row -> top4 per row, kept in smem ----
    float* mv = reinterpret_cast<float*>(sm);            // 16*128 floats = 8KB
    int*   mi = reinterpret_cast<int*>(sm + 8192);       // 8KB
    int*   candS = reinterpret_cast<int*>(sm + 16384);   // 512 ints = 2KB
    const int owner = warpN * 4 + tg;                    // 0..7
#pragma unroll
    for (int sl = 0; sl < 4; ++sl) {
        const int srow = warpM * 32 + (sl >> 1) * 16 + (sl & 1) * 8 + g;
#pragma unroll
        for (int j = 0; j < 2; ++j) {
            mv[(owner * 2 + j) * 128 + srow] = bv[sl][j];
            mi[(owner * 2 + j) * 128 + srow] = bi[sl][j];
        }
    }
    __syncthreads();
    if (tid < 128) {
        float fv0=-3.4e38f, fv1=-3.4e38f, fv2=-3.4e38f, fv3=-3.4e38f;
        int   fi0=0, fi1=0, fi2=0, fi3=0;
#pragma unroll
        for (int e = 0; e < 16; ++e) {
            float v = mv[e * 128 + tid];
            if (v > fv3) {
                int ci = mi[e * 128 + tid];
                if (v > fv0)      { fv3=fv2;fi3=fi2; fv2=fv1;fi2=fi1; fv1=fv0;fi1=fi0; fv0=v;fi0=ci; }
                else if (v > fv1) { fv3=fv2;fi3=fi2; fv2=fv1;fi2=fi1; fv1=v;fi1=ci; }
                else if (v > fv2) { fv3=fv2;fi3=fi2; fv2=v;fi2=ci; }
                else              { fv3=v;fi3=ci; }
            }
        }
        candS[tid * 4 + 0] = fi0;
        candS[tid * 4 + 1] = fi1;
        candS[tid * 4 + 2] = fi2;
        candS[tid * 4 + 3] = fi3;
    }
    __syncthreads();

    // ---- in-kernel exact rescore: 512 jobs over 256 threads (2 each) ----
    // Bit-identical to the R1 full scan: A = sequential sum(z^2), dot =
    // sequential fmaf, score = fl(fl(A-2B)+C); min-by-(value,index).
#pragma unroll
    for (int half = 0; half < 2; ++half) {
        const int j = tid + half * 256;       // job id 0..511
        const int row = j >> 2, m = j & 3;    // local row, candidate slot
        int c = candS[j];
        const float4* zr = reinterpret_cast<const float4*>(z + (size_t)(row0 + row) * D);
        const float4* cr = reinterpret_cast<const float4*>(cb + (size_t)c * D);
        float A = 0.f, acc2 = 0.f;
#pragma unroll 8
        for (int i = 0; i < D / 4; ++i) {
            float4 a = __ldg(zr + i);
            float4 b = __ldg(cr + i);
            A = __fadd_rn(A, __fmul_rn(a.x, a.x));
            A = __fadd_rn(A, __fmul_rn(a.y, a.y));
            A = __fadd_rn(A, __fmul_rn(a.z, a.z));
            A = __fadd_rn(A, __fmul_rn(a.w, a.w));
            acc2 = __fmaf_rn(a.x, b.x, acc2);
            acc2 = __fmaf_rn(a.y, b.y, acc2);
            acc2 = __fmaf_rn(a.z, b.z, acc2);
            acc2 = __fmaf_rn(a.w, b.w, acc2);
        }
        float s = __fadd_rn(__fmaf_rn(-2.f, acc2, A), g_C[c]);
#pragma unroll
        for (int o = 1; o < 4; o <<= 1) {
            float sv = __shfl_xor_sync(0xffffffffu, s, o);
            int   ci = __shfl_xor_sync(0xffffffffu, c, o);
            if (sv < s || (sv == s && ci < c)) { s = sv; c = ci; }
        }
        if (m == 0) g_idx[row0 + row] = c;
    }
}

// ================= finish: gather, z_q, per-row d^2, indices =================
// (R15 version, verbatim — original warp-tree ssum reduction, bit-exact.)
__global__ void k_finish(const float* __restrict__ z, const float* __restrict__ cb,
                         float* __restrict__ zq, float* __restrict__ idxout) {
    const int row = blockIdx.x;
    const int t = threadIdx.x;          // 128 threads, 2 elems each
    const int code = g_idx[row];
    const float2 zp = reinterpret_cast<const float2*>(z + (size_t)row * D)[t];
    const float2 cp = reinterpret_cast<const float2*>(cb + (size_t)code * D)[t];
    float d0 = __fsub_rn(cp.x, zp.x);
    float d1 = __fsub_rn(cp.y, zp.y);
    float ss = __fadd_rn(__fmul_rn(d0, d0), __fmul_rn(d1, d1));

    __shared__ float red[4];
#pragma unroll
    for (int o = 16; o > 0; o >>= 1)
        ss = __fadd_rn(ss, __shfl_xor_sync(0xffffffffu, ss, o));
    if ((t & 31) == 0) red[t >> 5] = ss;
    __syncthreads();
    float ssum = __fadd_rn(__fadd_rn(red[0], red[1]), __fadd_rn(red[2], red[3]));

    float mag = __fsqrt_rn(ssum);
    float den = __fadd_rn(mag, 1e-8f);
    float q0 = __fadd_rn(zp.x, __fmul_rn(mag, __fdiv_rn(d0, den)));
    float q1 = __fadd_rn(zp.y, __fmul_rn(mag, __fdiv_rn(d1, den)));
    float2 o; o.x = q0; o.y = q1;
    reinterpret_cast<float2*>(zq + (size_t)row * D)[t] = o;
    if (t == 0) {
        g_rowss[row] = ssum;
        idxout[row] = (float)code;
    }
}

// ====== loss: 64 blocks, fixed-order partials; last block does final sum ======
__global__ void k_loss(float* __restrict__ out_loss, int n) {
    const int b = blockIdx.x;              // 0..63
    const int per = n / 64;                // 256 rows per block
    __shared__ double sred[256];
    __shared__ bool amLast;
    double s = 0.0;
    for (int i = threadIdx.x; i < per; i += 256) s += (double)g_rowss[b * per + i];
    sred[threadIdx.x] = s;
    __syncthreads();
    for (int o = 128; o > 0; o >>= 1) {
        if (threadIdx.x < o) sred[threadIdx.x] += sred[threadIdx.x + o];
        __syncthreads();
    }
    if (threadIdx.x == 0) {
        g_part[b] = sred[0];
        __threadfence();
        unsigned int prev = atomicAdd(&g_done, 1u);
        amLast = (prev == 63u);
    }
    __syncthreads();
    if (amLast && threadIdx.x == 0) {
        double t = 0.0;
        for (int i = 0; i < 64; ++i) t += g_part[i];   // fixed order -> deterministic
        double mean = t / ((double)n * (double)D);
        out_loss[0] = (float)(1.25 * mean);
        g_done = 0;                                    // reset for next replay
    }
}

extern "C" void kernel_launch(void* const* d_in, const int* in_sizes, int n_in,
                              void* d_out, int out_size) {
    const float* z  = (const float*)d_in[0];
    const float* cb = (const float*)d_in[1];
    const int n = in_sizes[0] / D;   // 16384
    const int K = in_sizes[1] / D;   // 8192

    float* out    = (float*)d_out;
    float* zq     = out;
    float* loss   = out + (size_t)n * D;
    float* idxout = loss + 1;

    cudaFuncSetAttribute(k_gemm_topk, cudaFuncAttributeMaxDynamicSharedMemorySize, SM_TOT);

    const int nz4 = n * D / 4, nc4 = K * D / 4;
    const int ncvt = (nz4 + nc4 + 255) / 256;
    const int nsq  = (K + 255) / 256;
    k_prep<<<ncvt + nsq, 256>>>(z, cb, nz4, nc4, ncvt, K);
    k_gemm_topk<<<n / 128, 256, SM_TOT>>>(z, cb, K);
    k_finish<<<n, 128>>>(z, cb, zq, idxout);
    k_loss<<<64, 256>>>(loss, n);
}